// round 3
// baseline (speedup 1.0000x reference)
#include <cuda_runtime.h>
#include <cstdint>

// ---------------- problem constants ----------------
static constexpr int NIMG = 8192;      // B*N
static constexpr int PIX  = 81;        // 9x9
static constexpr int BATCH = 64;
static constexpr int NAGENT = 128;
static constexpr int ENCF = 128;
static constexpr int KDIM = 10368;     // 128*81
static constexpr float BN_EPS = 1e-5f;
static constexpr float INV_CNT = 1.0f / (8192.0f * 81.0f);

// ---------------- device scratch ----------------
__device__ float d_conv1[NIMG * 32 * PIX];
__device__ float d_conv2[NIMG * 64 * PIX];
__device__ float d_conv3[NIMG * 128 * PIX];
__device__ float d_part[2 * NIMG * ENCF];
__device__ float d_xcat1[BATCH * 384 * NAGENT];
__device__ float d_xcat2[BATCH * 384 * NAGENT];
__device__ float d_xg2[BATCH * 128 * NAGENT];
__device__ float d_gsum[384];
__device__ float d_gsq[384];
__device__ float d_bnA[384];
__device__ float d_bnB[384];

// ---------------- packed f32x2 helpers ----------------
__device__ __forceinline__ unsigned long long pk2(float lo, float hi) {
    unsigned long long r;
    asm("mov.b64 %0, {%1, %2};" : "=l"(r) : "f"(lo), "f"(hi));
    return r;
}
__device__ __forceinline__ unsigned long long bc2(float v) {
    unsigned long long r;
    asm("mov.b64 %0, {%1, %1};" : "=l"(r) : "f"(v));
    return r;
}
__device__ __forceinline__ void fma2(unsigned long long& d, unsigned long long a,
                                     unsigned long long b) {
    asm("fma.rn.f32x2 %0, %1, %2, %0;" : "+l"(d) : "l"(a), "l"(b));
}
__device__ __forceinline__ void add2(unsigned long long& d, unsigned long long a) {
    asm("add.rn.f32x2 %0, %0, %1;" : "+l"(d) : "l"(a));
}
__device__ __forceinline__ float2 upk2(unsigned long long v) {
    float lo, hi;
    asm("mov.b64 {%0, %1}, %2;" : "=f"(lo), "=f"(hi) : "l"(v));
    return make_float2(lo, hi);
}

// ---------------- fused (BN+ReLU of prev layer) + conv + BN-stats ----------------
template <int CIN, int COUT_T, int CG, int IPB, bool BN>
__global__ void conv_bn_stats_kernel(const float* __restrict__ gin,
                                     const float* __restrict__ gw,
                                     const float* __restrict__ bnA,
                                     const float* __restrict__ bnB,
                                     float* __restrict__ gout,
                                     float* __restrict__ gsum,
                                     float* __restrict__ gsq,
                                     int cout_total) {
    constexpr int TASKS = (COUT_T / CG) * 9;
    constexpr int WROW = CIN * 9;
    constexpr int WSTR = (WROW % 2 == 0) ? (WROW + 1) : (WROW + 2);
    constexpr int CG2 = CG / 2;
    extern __shared__ float sm[];
    float* w_s  = sm;                        // COUT_T * WSTR
    float* in_s = w_s + COUT_T * WSTR;       // IPB * CIN * 121
    float* red  = in_s + IPB * CIN * 121;    // 2 * COUT_T

    const int tx = threadIdx.x;
    const int ty = threadIdx.y;
    const int tid = ty * TASKS + tx;
    const int nthr = TASKS * IPB;
    const int img = blockIdx.x * IPB + ty;
    const int co_base = blockIdx.y * COUT_T;

    for (int idx = tid; idx < COUT_T * WROW; idx += nthr) {
        int co = idx / WROW, r = idx - co * WROW;
        w_s[co * WSTR + r] = gw[(co_base + co) * WROW + r];
    }
    for (int idx = tid; idx < 2 * COUT_T; idx += nthr) red[idx] = 0.f;
    for (int idx = tid; idx < IPB * CIN * 121; idx += nthr) in_s[idx] = 0.f;
    __syncthreads();
    {
        const float* ip = gin + (long long)img * (CIN * 81);
        float* is = in_s + ty * (CIN * 121);
        for (int idx = tx; idx < CIN * 81; idx += TASKS) {
            int ch = idx / 81, p = idx - ch * 81;
            int y = p / 9, x = p - y * 9;
            float v = ip[idx];
            if (BN) v = fmaxf(fmaf(bnA[ch], v, bnB[ch]), 0.f);
            is[ch * 121 + (y + 1) * 11 + (x + 1)] = v;
        }
    }
    __syncthreads();

    const int grp = tx / 9;
    const int y = tx - grp * 9;
    unsigned long long acc2[CG2][9];
#pragma unroll
    for (int j = 0; j < CG2; j++)
#pragma unroll
        for (int x = 0; x < 9; x++) acc2[j][x] = 0ull;

    const float* is = in_s + ty * (CIN * 121);
    for (int ci = 0; ci < CIN; ci++) {
        const float* rp = is + ci * 121 + y * 11;
        unsigned long long b0[11], b1[11], b2[11];
#pragma unroll
        for (int x = 0; x < 11; x++) {
            b0[x] = bc2(rp[x]);
            b1[x] = bc2(rp[11 + x]);
            b2[x] = bc2(rp[22 + x]);
        }
#pragma unroll
        for (int j = 0; j < CG2; j++) {
            const float* wp = w_s + (grp * CG + 2 * j) * WSTR + ci * 9;
            const float* wq = wp + WSTR;
            unsigned long long w[9];
#pragma unroll
            for (int t = 0; t < 9; t++) w[t] = pk2(wp[t], wq[t]);
#pragma unroll
            for (int x = 0; x < 9; x++) {
                fma2(acc2[j][x], b0[x],     w[0]);
                fma2(acc2[j][x], b0[x + 1], w[1]);
                fma2(acc2[j][x], b0[x + 2], w[2]);
                fma2(acc2[j][x], b1[x],     w[3]);
                fma2(acc2[j][x], b1[x + 1], w[4]);
                fma2(acc2[j][x], b1[x + 2], w[5]);
                fma2(acc2[j][x], b2[x],     w[6]);
                fma2(acc2[j][x], b2[x + 1], w[7]);
                fma2(acc2[j][x], b2[x + 2], w[8]);
            }
        }
    }

#pragma unroll
    for (int j = 0; j < CG2; j++) {
        int co0 = co_base + grp * CG + 2 * j;
        float* op0 = gout + ((long long)img * cout_total + co0) * 81 + y * 9;
        float* op1 = op0 + 81;
        unsigned long long s2 = 0ull, q2 = 0ull;
#pragma unroll
        for (int x = 0; x < 9; x++) {
            unsigned long long v = acc2[j][x];
            float2 f = upk2(v);
            op0[x] = f.x;
            op1[x] = f.y;
            add2(s2, v);
            fma2(q2, v, v);
        }
        float2 s = upk2(s2), q = upk2(q2);
        atomicAdd(&red[grp * CG + 2 * j], s.x);
        atomicAdd(&red[grp * CG + 2 * j + 1], s.y);
        atomicAdd(&red[COUT_T + grp * CG + 2 * j], q.x);
        atomicAdd(&red[COUT_T + grp * CG + 2 * j + 1], q.y);
    }
    __syncthreads();
    for (int idx = tid; idx < COUT_T; idx += nthr) {
        atomicAdd(&gsum[co_base + idx], red[idx]);
        atomicAdd(&gsq[co_base + idx], red[COUT_T + idx]);
    }
}

// ---------------- BN helpers ----------------
__global__ void zero_stats_kernel(float* gsum, float* gsq) {
    int t = threadIdx.x;
    if (t < 384) { gsum[t] = 0.f; gsq[t] = 0.f; }
}

__global__ void bn_prep_kernel(const float* gsum, const float* gsq,
                               const float* gamma, const float* beta,
                               float* a, float* b, int C) {
    int c = threadIdx.x;
    if (c < C) {
        float mu = gsum[c] * INV_CNT;
        float var = gsq[c] * INV_CNT - mu * mu;
        float ai = gamma[c] * rsqrtf(var + BN_EPS);
        a[c] = ai;
        b[c] = beta[c] - mu * ai;
    }
}

// ---------------- encoder GEMM (BN+ReLU fused on A), split-K=2, packed ----------------
__global__ void gemm_enc_kernel(const float* __restrict__ A, const float* __restrict__ W,
                                const float* __restrict__ bnA, const float* __restrict__ bnB,
                                float* __restrict__ part) {
    __shared__ float As[64][17];
    __shared__ float Ws[128][17];
    const int tx = threadIdx.x;
    const int mb = blockIdx.x * 64;
    const int ks = blockIdx.z;
    const int k0 = ks * 5184;

    unsigned long long acc2[8][2];
#pragma unroll
    for (int i = 0; i < 8; i++) { acc2[i][0] = 0ull; acc2[i][1] = 0ull; }

    const int mi = tx >> 5;
    const int ej = tx & 31;

    for (int t = 0; t < 324; t++) {
        int kb = k0 + t * 16;
#pragma unroll
        for (int l = 0; l < 4; l++) {
            int idx = tx + l * 256;
            int r = idx >> 4, c = idx & 15;
            float v = A[(long long)(mb + r) * KDIM + kb + c];
            int ch = (kb + c) / 81;
            As[r][c] = fmaxf(fmaf(bnA[ch], v, bnB[ch]), 0.f);
        }
#pragma unroll
        for (int l = 0; l < 8; l++) {
            int idx = tx + l * 256;
            int r = idx >> 4, c = idx & 15;
            Ws[r][c] = W[(long long)r * KDIM + kb + c];
        }
        __syncthreads();
#pragma unroll
        for (int k = 0; k < 16; k++) {
            unsigned long long wp0 = pk2(Ws[ej][k], Ws[ej + 32][k]);
            unsigned long long wp1 = pk2(Ws[ej + 64][k], Ws[ej + 96][k]);
#pragma unroll
            for (int i = 0; i < 8; i++) {
                unsigned long long ap = bc2(As[mi + 8 * i][k]);
                fma2(acc2[i][0], ap, wp0);
                fma2(acc2[i][1], ap, wp1);
            }
        }
        __syncthreads();
    }
#pragma unroll
    for (int i = 0; i < 8; i++) {
        float2 v0 = upk2(acc2[i][0]);
        float2 v1 = upk2(acc2[i][1]);
        float* pp = part + ks * (NIMG * ENCF) + (mb + mi + 8 * i) * ENCF + ej;
        pp[0] = v0.x; pp[32] = v0.y; pp[64] = v1.x; pp[96] = v1.y;
    }
}

__global__ void combine_enc_kernel(const float* __restrict__ part, const float* __restrict__ enc_b,
                                   float* __restrict__ xcat) {
    int idx = blockIdx.x * 256 + threadIdx.x;
    int e = idx & 127;
    int m = idx >> 7;
    int b = m >> 7;
    int n = m & 127;
    float v = part[idx] + part[NIMG * ENCF + idx] + enc_b[e];
    xcat[b * (384 * 128) + e * 128 + n] = v;
}

// ---------------- batched X*S and X*S^2 ----------------
__global__ void xs_kernel(float* __restrict__ xcat, const float* __restrict__ gso) {
    extern __shared__ float sm[];
    float (*Xs)[129] = (float (*)[129])sm;
    float (*Ss)[129] = (float (*)[129])(sm + 128 * 129);
    const int b = blockIdx.x, tx = threadIdx.x;

    for (int l = 0; l < 64; l++) {
        int idx = tx + l * 256;
        int r = idx >> 7, c = idx & 127;
        Ss[r][c] = gso[b * 16384 + idx];
        Xs[r][c] = xcat[b * (384 * 128) + idx];
    }
    __syncthreads();

    const int nj = tx & 15;
    const int fi = tx >> 4;
    unsigned long long acc2[8][4];

    for (int pass = 0; pass < 2; pass++) {
#pragma unroll
        for (int i = 0; i < 8; i++)
#pragma unroll
            for (int j = 0; j < 4; j++) acc2[i][j] = 0ull;
        for (int n = 0; n < 128; n++) {
            unsigned long long sp[4];
#pragma unroll
            for (int j = 0; j < 4; j++)
                sp[j] = pk2(Ss[n][nj + 32 * j], Ss[n][nj + 16 + 32 * j]);
#pragma unroll
            for (int i = 0; i < 8; i++) {
                unsigned long long xb = bc2(Xs[fi + 16 * i][n]);
#pragma unroll
                for (int j = 0; j < 4; j++) fma2(acc2[i][j], xb, sp[j]);
            }
        }
        __syncthreads();
        float* gdst = xcat + b * (384 * 128) + (pass + 1) * 16384;
#pragma unroll
        for (int i = 0; i < 8; i++)
#pragma unroll
            for (int j = 0; j < 4; j++) {
                float2 v = upk2(acc2[i][j]);
                int f = fi + 16 * i;
                Xs[f][nj + 32 * j] = v.x;
                Xs[f][nj + 16 + 32 * j] = v.y;
                gdst[f * 128 + nj + 32 * j] = v.x;
                gdst[f * 128 + nj + 16 + 32 * j] = v.y;
            }
        __syncthreads();
    }
}

// ---------------- graph-filter GEMM ----------------
__global__ void gfilter_kernel(const float* __restrict__ xcat, const float* __restrict__ W,
                               const float* __restrict__ bias, float* __restrict__ out,
                               int out_stride) {
    extern __shared__ float sm[];
    float (*Ws)[97] = (float (*)[97])sm;
    float (*Xs)[129] = (float (*)[129])(sm + 128 * 97);
    const int b = blockIdx.x, tx = threadIdx.x;
    const int nj = tx & 15;
    const int gi = tx >> 4;

    unsigned long long acc2[8][4];
#pragma unroll
    for (int i = 0; i < 8; i++)
#pragma unroll
        for (int j = 0; j < 4; j++) acc2[i][j] = 0ull;

    for (int kt = 0; kt < 4; kt++) {
        for (int l = 0; l < 48; l++) {
            int idx = tx + l * 256;
            int g = idx / 96, kc = idx - g * 96;
            int kg = kt * 96 + kc;
            Ws[g][kc] = W[(kg >> 7) * 16384 + g * 128 + (kg & 127)];
        }
        for (int l = 0; l < 48; l++) {
            int idx = tx + l * 256;
            int r = idx >> 7, c = idx & 127;
            Xs[r][c] = xcat[b * (384 * 128) + (kt * 96 + r) * 128 + c];
        }
        __syncthreads();
        for (int kc = 0; kc < 96; kc++) {
            unsigned long long xp[4];
#pragma unroll
            for (int j = 0; j < 4; j++)
                xp[j] = pk2(Xs[kc][nj + 32 * j], Xs[kc][nj + 16 + 32 * j]);
#pragma unroll
            for (int i = 0; i < 8; i++) {
                unsigned long long wb = bc2(Ws[gi + 16 * i][kc]);
#pragma unroll
                for (int j = 0; j < 4; j++) fma2(acc2[i][j], wb, xp[j]);
            }
        }
        __syncthreads();
    }
#pragma unroll
    for (int i = 0; i < 8; i++) {
        int g = gi + 16 * i;
        float bb = bias[g];
#pragma unroll
        for (int j = 0; j < 4; j++) {
            float2 v = upk2(acc2[i][j]);
            out[b * out_stride + g * 128 + nj + 32 * j] = fmaxf(v.x + bb, 0.f);
            out[b * out_stride + g * 128 + nj + 16 + 32 * j] = fmaxf(v.y + bb, 0.f);
        }
    }
}

// ---------------- action head (smem-staged; FIXED weight staging) ----------------
__global__ void act_kernel(const float* __restrict__ xg2, const float* __restrict__ aw,
                           const float* __restrict__ ab, float* __restrict__ out) {
    extern __shared__ float sm[];
    float* xs = sm;          // 16384 floats
    float* ws = sm + 16384;  // 640 floats
    const int b = blockIdx.x, t = threadIdx.x;
    for (int i = t; i < 16384; i += 256) xs[i] = xg2[b * 16384 + i];
    for (int i = t; i < 640; i += 256) ws[i] = aw[i];   // <-- fixed: full 5*128 staged
    __syncthreads();
    for (int o = t; o < 640; o += 256) {
        int a = o % 5, n = o / 5;
        float s = ab[a];
        const float* wp = ws + a * 128;
        const float* xp = xs + n;
#pragma unroll 8
        for (int g = 0; g < 128; g++) s = fmaf(xp[g * 128], wp[g], s);
        out[b * 640 + o] = s;
    }
}

// ---------------- host launcher ----------------
extern "C" void kernel_launch(void* const* d_in, const int* in_sizes, int n_in,
                              void* d_out, int out_size) {
    (void)in_sizes; (void)n_in; (void)out_size;
    const float* states = (const float*)d_in[0];
    const float* gso    = (const float*)d_in[1];
    const float* c1_w = (const float*)d_in[2];
    const float* c1_g = (const float*)d_in[4];
    const float* c1_be = (const float*)d_in[5];
    const float* c2_w = (const float*)d_in[6];
    const float* c2_g = (const float*)d_in[8];
    const float* c2_be = (const float*)d_in[9];
    const float* c3_w = (const float*)d_in[10];
    const float* c3_g = (const float*)d_in[12];
    const float* c3_be = (const float*)d_in[13];
    const float* enc_w = (const float*)d_in[14];
    const float* enc_b = (const float*)d_in[15];
    const float* g1_w = (const float*)d_in[16];
    const float* g1_b = (const float*)d_in[17];
    const float* g2_w = (const float*)d_in[18];
    const float* g2_b = (const float*)d_in[19];
    const float* act_w = (const float*)d_in[20];
    const float* act_b = (const float*)d_in[21];
    float* out = (float*)d_out;

    void *p1, *p2, *p3, *ppart, *pxc1, *pxc2, *pxg2, *psum, *psq, *pA, *pB;
    cudaGetSymbolAddress(&p1, d_conv1);
    cudaGetSymbolAddress(&p2, d_conv2);
    cudaGetSymbolAddress(&p3, d_conv3);
    cudaGetSymbolAddress(&ppart, d_part);
    cudaGetSymbolAddress(&pxc1, d_xcat1);
    cudaGetSymbolAddress(&pxc2, d_xcat2);
    cudaGetSymbolAddress(&pxg2, d_xg2);
    cudaGetSymbolAddress(&psum, d_gsum);
    cudaGetSymbolAddress(&psq, d_gsq);
    cudaGetSymbolAddress(&pA, d_bnA);
    cudaGetSymbolAddress(&pB, d_bnB);
    float* conv1 = (float*)p1;
    float* conv2 = (float*)p2;
    float* conv3 = (float*)p3;
    float* part = (float*)ppart;
    float* xcat1 = (float*)pxc1;
    float* xcat2 = (float*)pxc2;
    float* xg2 = (float*)pxg2;
    float* gsum = (float*)psum;
    float* gsq = (float*)psq;
    float* bnA = (float*)pA;
    float* bnB = (float*)pB;

    const int SM1 = (32 * 29 + 4 * 3 * 121 + 64) * 4;
    const int SM2 = (64 * 289 + 2 * 32 * 121 + 128) * 4;
    const int SM3 = (64 * 577 + 2 * 64 * 121 + 128) * 4;
    const int XS_SMEM = 2 * 128 * 129 * 4;
    const int GF_SMEM = (128 * 97 + 96 * 129) * 4;
    const int ACT_SMEM = (16384 + 640) * 4;

    cudaFuncSetAttribute(conv_bn_stats_kernel<3, 32, 4, 4, false>,
                         cudaFuncAttributeMaxDynamicSharedMemorySize, SM1);
    cudaFuncSetAttribute(conv_bn_stats_kernel<32, 64, 4, 2, true>,
                         cudaFuncAttributeMaxDynamicSharedMemorySize, SM2);
    cudaFuncSetAttribute(conv_bn_stats_kernel<64, 64, 4, 2, true>,
                         cudaFuncAttributeMaxDynamicSharedMemorySize, SM3);
    cudaFuncSetAttribute(xs_kernel, cudaFuncAttributeMaxDynamicSharedMemorySize, XS_SMEM);
    cudaFuncSetAttribute(gfilter_kernel, cudaFuncAttributeMaxDynamicSharedMemorySize, GF_SMEM);
    cudaFuncSetAttribute(act_kernel, cudaFuncAttributeMaxDynamicSharedMemorySize, ACT_SMEM);

    zero_stats_kernel<<<1, 384>>>(gsum, gsq);

    conv_bn_stats_kernel<3, 32, 4, 4, false>
        <<<dim3(NIMG / 4, 1), dim3(72, 4), SM1>>>(states, c1_w, nullptr, nullptr,
                                                  conv1, gsum, gsq, 32);
    bn_prep_kernel<<<1, 128>>>(gsum, gsq, c1_g, c1_be, bnA, bnB, 32);

    conv_bn_stats_kernel<32, 64, 4, 2, true>
        <<<dim3(NIMG / 2, 1), dim3(144, 2), SM2>>>(conv1, c2_w, bnA, bnB,
                                                   conv2, gsum + 128, gsq + 128, 64);
    bn_prep_kernel<<<1, 128>>>(gsum + 128, gsq + 128, c2_g, c2_be, bnA + 128, bnB + 128, 64);

    conv_bn_stats_kernel<64, 64, 4, 2, true>
        <<<dim3(NIMG / 2, 2), dim3(144, 2), SM3>>>(conv2, c3_w, bnA + 128, bnB + 128,
                                                   conv3, gsum + 256, gsq + 256, 128);
    bn_prep_kernel<<<1, 128>>>(gsum + 256, gsq + 256, c3_g, c3_be, bnA + 256, bnB + 256, 128);

    gemm_enc_kernel<<<dim3(128, 1, 2), 256>>>(conv3, enc_w, bnA + 256, bnB + 256, part);
    combine_enc_kernel<<<4096, 256>>>(part, enc_b, xcat1);

    xs_kernel<<<BATCH, 256, XS_SMEM>>>(xcat1, gso);
    gfilter_kernel<<<BATCH, 256, GF_SMEM>>>(xcat1, g1_w, g1_b, xcat2, 384 * 128);

    xs_kernel<<<BATCH, 256, XS_SMEM>>>(xcat2, gso);
    gfilter_kernel<<<BATCH, 256, GF_SMEM>>>(xcat2, g2_w, g2_b, xg2, 128 * 128);

    act_kernel<<<BATCH, 256, ACT_SMEM>>>(xg2, act_w, act_b, out);
}